// round 1
// baseline (speedup 1.0000x reference)
#include <cuda_runtime.h>
#include <cuda_bf16.h>
#include <math.h>

// Problem constants
constexpr int BATCH    = 2;
constexpr int SEQ      = 2048;
constexpr int D_MODEL  = 1024;
constexpr int N_HEADS  = 16;
constexpr int HEAD_DIM = 64;
constexpr int MROWS    = BATCH * SEQ;   // 4096

// ---------------------------------------------------------------------------
// Device scratch (allocations are forbidden; use __device__ globals)
// ---------------------------------------------------------------------------
__device__ float g_Q[BATCH * N_HEADS * SEQ * HEAD_DIM];   // [B,H,S,hd]
__device__ float g_K[BATCH * N_HEADS * SEQ * HEAD_DIM];
__device__ float g_V[BATCH * N_HEADS * SEQ * HEAD_DIM];
__device__ float g_Ctx[BATCH * SEQ * D_MODEL];            // [B,S,D] (heads concatenated)

// ---------------------------------------------------------------------------
// Kernel 1: fused QKV projection.
// grid = (MROWS/128, 3*N_HEADS). blockIdx.y = mat*16 + h.
// Each block: 128 rows of X  x  the [1024 x 64] weight of one head/matrix.
// 256 threads, per-thread 8x4 microtile.
// ---------------------------------------------------------------------------
__global__ __launch_bounds__(256) void qkv_kernel(
    const float* __restrict__ X,
    const float* __restrict__ Wq, const float* __restrict__ Wk, const float* __restrict__ Wv,
    const float* __restrict__ bq, const float* __restrict__ bk, const float* __restrict__ bv)
{
    __shared__ float AsT[16][128];   // A transposed: [k][m]
    __shared__ float Bs[16][64];     // B: [k][n]

    const int tid = threadIdx.x;
    const int mt  = blockIdx.x;
    const int yy  = blockIdx.y;
    const int mat = yy >> 4;
    const int h   = yy & 15;

    const float* W;  const float* bias;  float* Out;
    if (mat == 0)      { W = Wq; bias = bq; Out = g_Q; }
    else if (mat == 1) { W = Wk; bias = bk; Out = g_K; }
    else               { W = Wv; bias = bv; Out = g_V; }
    W    += h * D_MODEL * HEAD_DIM;   // [1024, 64] row-major
    bias += h * HEAD_DIM;

    const int m0  = mt * 128;
    const int tx  = tid & 15;         // N direction (4 cols)
    const int ty  = tid >> 4;         // M direction (8 rows)

    // load mappings
    const int arow = tid & 127;          // 0..127
    const int ac0  = (tid >> 7) * 8;     // 0 or 8
    const int brow = tid >> 4;           // 0..15
    const int bc0  = (tid & 15) * 4;     // 0..60

    float acc[8][4];
#pragma unroll
    for (int i = 0; i < 8; i++)
#pragma unroll
        for (int j = 0; j < 4; j++) acc[i][j] = 0.f;

    const float* Aptr = X + (size_t)(m0 + arow) * D_MODEL + ac0;
    const float* Bptr = W + brow * HEAD_DIM + bc0;

    for (int k0 = 0; k0 < D_MODEL; k0 += 16) {
        float4 a0 = *(const float4*)(Aptr + k0);
        float4 a1 = *(const float4*)(Aptr + k0 + 4);
        float4 b  = *(const float4*)(Bptr + (size_t)k0 * HEAD_DIM);

        AsT[ac0 + 0][arow] = a0.x;  AsT[ac0 + 1][arow] = a0.y;
        AsT[ac0 + 2][arow] = a0.z;  AsT[ac0 + 3][arow] = a0.w;
        AsT[ac0 + 4][arow] = a1.x;  AsT[ac0 + 5][arow] = a1.y;
        AsT[ac0 + 6][arow] = a1.z;  AsT[ac0 + 7][arow] = a1.w;
        *(float4*)&Bs[brow][bc0] = b;
        __syncthreads();

#pragma unroll
        for (int kk = 0; kk < 16; kk++) {
            float a[8], bb[4];
#pragma unroll
            for (int i = 0; i < 8; i++) a[i] = AsT[kk][ty * 8 + i];
#pragma unroll
            for (int j = 0; j < 4; j++) bb[j] = Bs[kk][tx * 4 + j];
#pragma unroll
            for (int i = 0; i < 8; i++)
#pragma unroll
                for (int j = 0; j < 4; j++)
                    acc[i][j] += a[i] * bb[j];
        }
        __syncthreads();
    }

    float bv4[4];
#pragma unroll
    for (int j = 0; j < 4; j++) bv4[j] = bias[tx * 4 + j];

#pragma unroll
    for (int i = 0; i < 8; i++) {
        const int m = m0 + ty * 8 + i;
        const int b = m >> 11;          // m / SEQ
        const int s = m & 2047;         // m % SEQ
        float4 v;
        v.x = acc[i][0] + bv4[0];
        v.y = acc[i][1] + bv4[1];
        v.z = acc[i][2] + bv4[2];
        v.w = acc[i][3] + bv4[3];
        float* dst = Out + (((size_t)(b * N_HEADS + h) * SEQ + s) * HEAD_DIM) + tx * 4;
        *(float4*)dst = v;
    }
}

// ---------------------------------------------------------------------------
// Kernel 2: causal flash attention (fp32).
// grid = (SEQ/64, BATCH*N_HEADS). One block: 64 query rows of one (b,h).
// 256 threads: thread t -> row r = t/4, column/dim group g = t%4.
// Smem rows padded to 68 floats (keeps 16B alignment, kills bank aliasing).
// ---------------------------------------------------------------------------
constexpr int PITCH = 68;
constexpr int ATT_SMEM_BYTES = 4 * 64 * PITCH * (int)sizeof(float); // 69632

__global__ __launch_bounds__(256) void attn_kernel()
{
    extern __shared__ float sm[];
    float (*Qs)[PITCH] = (float(*)[PITCH])(sm);
    float (*Ks)[PITCH] = (float(*)[PITCH])(sm + 64 * PITCH);
    float (*Vs)[PITCH] = (float(*)[PITCH])(sm + 2 * 64 * PITCH);
    float (*Ps)[PITCH] = (float(*)[PITCH])(sm + 3 * 64 * PITCH);

    const int qt  = gridDim.x - 1 - blockIdx.x;  // big tiles first (load balance)
    const int bh  = blockIdx.y;
    const int tid = threadIdx.x;
    const int r   = tid >> 2;     // 0..63 (query row within tile)
    const int g   = tid & 3;      // 0..3  (16-wide column/dim group)

    const float* Qb = g_Q + (size_t)bh * SEQ * HEAD_DIM;
    const float* Kb = g_K + (size_t)bh * SEQ * HEAD_DIM;
    const float* Vb = g_V + (size_t)bh * SEQ * HEAD_DIM;

    const int qrow = qt * 64 + r;

    // load Q tile: thread loads row r, cols [g*16, g*16+16)
    {
        const float* src = Qb + (size_t)qrow * HEAD_DIM + g * 16;
#pragma unroll
        for (int j = 0; j < 4; j++)
            *(float4*)&Qs[r][g * 16 + 4 * j] = *(const float4*)(src + 4 * j);
    }

    float m_i = -1e30f, l_i = 0.f;
    float o[16];
#pragma unroll
    for (int e = 0; e < 16; e++) o[e] = 0.f;

    for (int kt = 0; kt <= qt; kt++) {
        // load K / V tiles
        {
            const float* ksrc = Kb + (size_t)(kt * 64 + r) * HEAD_DIM + g * 16;
            const float* vsrc = Vb + (size_t)(kt * 64 + r) * HEAD_DIM + g * 16;
#pragma unroll
            for (int j = 0; j < 4; j++) {
                *(float4*)&Ks[r][g * 16 + 4 * j] = *(const float4*)(ksrc + 4 * j);
                *(float4*)&Vs[r][g * 16 + 4 * j] = *(const float4*)(vsrc + 4 * j);
            }
        }
        __syncthreads();

        // ---- scores: S[r][c] for c in [g*16, g*16+16) ----
        float s[16];
#pragma unroll 4
        for (int cc = 0; cc < 16; cc++) {
            const int c = g * 16 + cc;
            float4 av = make_float4(0.f, 0.f, 0.f, 0.f);
#pragma unroll
            for (int e4 = 0; e4 < 16; e4++) {
                float4 q = *(const float4*)&Qs[r][e4 * 4];
                float4 k = *(const float4*)&Ks[c][e4 * 4];
                av.x += q.x * k.x;  av.y += q.y * k.y;
                av.z += q.z * k.z;  av.w += q.w * k.w;
            }
            const float sc = (av.x + av.y + av.z + av.w) * 0.125f;  // 1/sqrt(64)
            const int kcol = kt * 64 + c;
            s[cc] = (kcol <= qrow) ? sc : -1e30f;
        }

        // ---- online softmax update (row = 4 lanes in same warp) ----
        float mnew = m_i;
#pragma unroll
        for (int cc = 0; cc < 16; cc++) mnew = fmaxf(mnew, s[cc]);
        mnew = fmaxf(mnew, __shfl_xor_sync(0xffffffffu, mnew, 1));
        mnew = fmaxf(mnew, __shfl_xor_sync(0xffffffffu, mnew, 2));

        const float corr = __expf(m_i - mnew);
        float lsum = 0.f;
#pragma unroll
        for (int cc = 0; cc < 16; cc++) {
            const float p = __expf(s[cc] - mnew);
            Ps[r][g * 16 + cc] = p;
            lsum += p;
        }
        lsum += __shfl_xor_sync(0xffffffffu, lsum, 1);
        lsum += __shfl_xor_sync(0xffffffffu, lsum, 2);
        l_i = l_i * corr + lsum;
        m_i = mnew;
#pragma unroll
        for (int e = 0; e < 16; e++) o[e] *= corr;
        __syncwarp();   // Ps produced/consumed within the same warp

        // ---- O += P * V : thread owns dims [g*16, g*16+16) of row r ----
#pragma unroll 16
        for (int c = 0; c < 64; c++) {
            const float p = Ps[r][c];
#pragma unroll
            for (int j = 0; j < 4; j++) {
                float4 v = *(const float4*)&Vs[c][g * 16 + 4 * j];
                o[4 * j + 0] += p * v.x;
                o[4 * j + 1] += p * v.y;
                o[4 * j + 2] += p * v.z;
                o[4 * j + 3] += p * v.w;
            }
        }
        __syncthreads();   // protect Ks/Vs before next tile's load
    }

    // finalize + write context directly in [B, S, D] layout
    const float inv = 1.f / l_i;
    const int b = bh >> 4;
    const int h = bh & 15;
    float* dst = g_Ctx + ((size_t)(b * SEQ + qrow) * D_MODEL) + h * HEAD_DIM + g * 16;
#pragma unroll
    for (int j = 0; j < 4; j++) {
        float4 v;
        v.x = o[4 * j + 0] * inv;
        v.y = o[4 * j + 1] * inv;
        v.z = o[4 * j + 2] * inv;
        v.w = o[4 * j + 3] * inv;
        *(float4*)(dst + 4 * j) = v;
    }
}

// ---------------------------------------------------------------------------
// Kernel 3: output projection. g_Ctx [4096 x 1024] @ Wo [1024 x 1024] + bo.
// grid = (MROWS/128, D_MODEL/64). Same microkernel as kernel 1.
// ---------------------------------------------------------------------------
__global__ __launch_bounds__(256) void oproj_kernel(
    const float* __restrict__ Wo, const float* __restrict__ bo,
    float* __restrict__ out)
{
    __shared__ float AsT[16][128];
    __shared__ float Bs[16][64];

    const int tid = threadIdx.x;
    const int mt  = blockIdx.x;
    const int n0  = blockIdx.y * 64;

    const int m0  = mt * 128;
    const int tx  = tid & 15;
    const int ty  = tid >> 4;

    const int arow = tid & 127;
    const int ac0  = (tid >> 7) * 8;
    const int brow = tid >> 4;
    const int bc0  = (tid & 15) * 4;

    float acc[8][4];
#pragma unroll
    for (int i = 0; i < 8; i++)
#pragma unroll
        for (int j = 0; j < 4; j++) acc[i][j] = 0.f;

    const float* Aptr = g_Ctx + (size_t)(m0 + arow) * D_MODEL + ac0;
    const float* Bptr = Wo + (size_t)brow * D_MODEL + n0 + bc0;

    for (int k0 = 0; k0 < D_MODEL; k0 += 16) {
        float4 a0 = *(const float4*)(Aptr + k0);
        float4 a1 = *(const float4*)(Aptr + k0 + 4);
        float4 b  = *(const float4*)(Bptr + (size_t)k0 * D_MODEL);

        AsT[ac0 + 0][arow] = a0.x;  AsT[ac0 + 1][arow] = a0.y;
        AsT[ac0 + 2][arow] = a0.z;  AsT[ac0 + 3][arow] = a0.w;
        AsT[ac0 + 4][arow] = a1.x;  AsT[ac0 + 5][arow] = a1.y;
        AsT[ac0 + 6][arow] = a1.z;  AsT[ac0 + 7][arow] = a1.w;
        *(float4*)&Bs[brow][bc0] = b;
        __syncthreads();

#pragma unroll
        for (int kk = 0; kk < 16; kk++) {
            float a[8], bb[4];
#pragma unroll
            for (int i = 0; i < 8; i++) a[i] = AsT[kk][ty * 8 + i];
#pragma unroll
            for (int j = 0; j < 4; j++) bb[j] = Bs[kk][tx * 4 + j];
#pragma unroll
            for (int i = 0; i < 8; i++)
#pragma unroll
                for (int j = 0; j < 4; j++)
                    acc[i][j] += a[i] * bb[j];
        }
        __syncthreads();
    }

    float bv4[4];
#pragma unroll
    for (int j = 0; j < 4; j++) bv4[j] = bo[n0 + tx * 4 + j];

#pragma unroll
    for (int i = 0; i < 8; i++) {
        const int m = m0 + ty * 8 + i;
        float4 v;
        v.x = acc[i][0] + bv4[0];
        v.y = acc[i][1] + bv4[1];
        v.z = acc[i][2] + bv4[2];
        v.w = acc[i][3] + bv4[3];
        *(float4*)(out + (size_t)m * D_MODEL + n0 + tx * 4) = v;
    }
}

// ---------------------------------------------------------------------------
// kernel_launch — graph-capturable, allocation-free.
// Input order (metadata): hidden_state, Wq, Wk, Wv, bq, bk, bv, Wo, bo
// ---------------------------------------------------------------------------
extern "C" void kernel_launch(void* const* d_in, const int* in_sizes, int n_in,
                              void* d_out, int out_size)
{
    const float* X  = (const float*)d_in[0];
    const float* Wq = (const float*)d_in[1];
    const float* Wk = (const float*)d_in[2];
    const float* Wv = (const float*)d_in[3];
    const float* bq = (const float*)d_in[4];
    const float* bk = (const float*)d_in[5];
    const float* bv = (const float*)d_in[6];
    const float* Wo = (const float*)d_in[7];
    const float* bo = (const float*)d_in[8];
    float* out = (float*)d_out;

    cudaFuncSetAttribute(attn_kernel,
                         cudaFuncAttributeMaxDynamicSharedMemorySize,
                         ATT_SMEM_BYTES);

    // 1) QKV projections
    {
        dim3 grid(MROWS / 128, 3 * N_HEADS);
        qkv_kernel<<<grid, 256>>>(X, Wq, Wk, Wv, bq, bk, bv);
    }
    // 2) causal flash attention
    {
        dim3 grid(SEQ / 64, BATCH * N_HEADS);
        attn_kernel<<<grid, 256, ATT_SMEM_BYTES>>>();
    }
    // 3) output projection
    {
        dim3 grid(MROWS / 128, D_MODEL / 64);
        oproj_kernel<<<grid, 256>>>(Wo, bo, out);
    }
}

// round 2
// speedup vs baseline: 2.8016x; 2.8016x over previous
#include <cuda_runtime.h>
#include <cuda_bf16.h>
#include <math.h>

// Problem constants
constexpr int BATCH    = 2;
constexpr int SEQ      = 2048;
constexpr int D_MODEL  = 1024;
constexpr int N_HEADS  = 16;
constexpr int HEAD_DIM = 64;
constexpr int MROWS    = BATCH * SEQ;   // 4096

// ---------------------------------------------------------------------------
// Device scratch (allocations are forbidden; use __device__ globals)
// ---------------------------------------------------------------------------
__device__ float g_Q[BATCH * N_HEADS * SEQ * HEAD_DIM];   // [B,H,S,hd]
__device__ float g_K[BATCH * N_HEADS * SEQ * HEAD_DIM];
__device__ float g_V[BATCH * N_HEADS * SEQ * HEAD_DIM];
__device__ float g_Ctx[BATCH * SEQ * D_MODEL];            // [B,S,D]

// ---------------------------------------------------------------------------
// Kernel 1: fused QKV projection (unchanged from round 1).
// ---------------------------------------------------------------------------
__global__ __launch_bounds__(256) void qkv_kernel(
    const float* __restrict__ X,
    const float* __restrict__ Wq, const float* __restrict__ Wk, const float* __restrict__ Wv,
    const float* __restrict__ bq, const float* __restrict__ bk, const float* __restrict__ bv)
{
    __shared__ float AsT[16][128];
    __shared__ float Bs[16][64];

    const int tid = threadIdx.x;
    const int mt  = blockIdx.x;
    const int yy  = blockIdx.y;
    const int mat = yy >> 4;
    const int h   = yy & 15;

    const float* W;  const float* bias;  float* Out;
    if (mat == 0)      { W = Wq; bias = bq; Out = g_Q; }
    else if (mat == 1) { W = Wk; bias = bk; Out = g_K; }
    else               { W = Wv; bias = bv; Out = g_V; }
    W    += h * D_MODEL * HEAD_DIM;
    bias += h * HEAD_DIM;

    const int m0  = mt * 128;
    const int tx  = tid & 15;
    const int ty  = tid >> 4;

    const int arow = tid & 127;
    const int ac0  = (tid >> 7) * 8;
    const int brow = tid >> 4;
    const int bc0  = (tid & 15) * 4;

    float acc[8][4];
#pragma unroll
    for (int i = 0; i < 8; i++)
#pragma unroll
        for (int j = 0; j < 4; j++) acc[i][j] = 0.f;

    const float* Aptr = X + (size_t)(m0 + arow) * D_MODEL + ac0;
    const float* Bptr = W + brow * HEAD_DIM + bc0;

    for (int k0 = 0; k0 < D_MODEL; k0 += 16) {
        float4 a0 = *(const float4*)(Aptr + k0);
        float4 a1 = *(const float4*)(Aptr + k0 + 4);
        float4 b  = *(const float4*)(Bptr + (size_t)k0 * HEAD_DIM);

        AsT[ac0 + 0][arow] = a0.x;  AsT[ac0 + 1][arow] = a0.y;
        AsT[ac0 + 2][arow] = a0.z;  AsT[ac0 + 3][arow] = a0.w;
        AsT[ac0 + 4][arow] = a1.x;  AsT[ac0 + 5][arow] = a1.y;
        AsT[ac0 + 6][arow] = a1.z;  AsT[ac0 + 7][arow] = a1.w;
        *(float4*)&Bs[brow][bc0] = b;
        __syncthreads();

#pragma unroll
        for (int kk = 0; kk < 16; kk++) {
            float a[8], bb[4];
#pragma unroll
            for (int i = 0; i < 8; i++) a[i] = AsT[kk][ty * 8 + i];
#pragma unroll
            for (int j = 0; j < 4; j++) bb[j] = Bs[kk][tx * 4 + j];
#pragma unroll
            for (int i = 0; i < 8; i++)
#pragma unroll
                for (int j = 0; j < 4; j++)
                    acc[i][j] += a[i] * bb[j];
        }
        __syncthreads();
    }

    float bv4[4];
#pragma unroll
    for (int j = 0; j < 4; j++) bv4[j] = bias[tx * 4 + j];

#pragma unroll
    for (int i = 0; i < 8; i++) {
        const int m = m0 + ty * 8 + i;
        const int b = m >> 11;
        const int s = m & 2047;
        float4 v;
        v.x = acc[i][0] + bv4[0];
        v.y = acc[i][1] + bv4[1];
        v.z = acc[i][2] + bv4[2];
        v.w = acc[i][3] + bv4[3];
        float* dst = Out + (((size_t)(b * N_HEADS + h) * SEQ + s) * HEAD_DIM) + tx * 4;
        *(float4*)dst = v;
    }
}

// ---------------------------------------------------------------------------
// Kernel 2 (REWRITTEN): causal flash attention, register-tiled fp32.
// Br=128 query rows per block, Bc=64 keys per tile. 256 threads.
// Thread grid 16(ty: 8 rows each) x 16(tx: 4 cols each); 8x4 microtile for
// both the QK^T GEMM and the P*V GEMM. Q and P stored transposed in smem so
// every inner step is 3 LDS.128 per 32 FMA.
// ---------------------------------------------------------------------------
constexpr int QP = 132;   // pitch for [e][r] / [c][r] arrays (r-dim 128 + pad)
constexpr int KP = 68;    // pitch for [e][c] / [c][e] arrays (64 + pad)

// smem layout (floats):
//   QsT [64][QP]   e-major, transposed Q
//   KsT [64][KP]   e-major, transposed K
//   Vs  [64][KP]   c-major, natural V
//   PsT [64][QP]   c-major, transposed P
constexpr int OFF_Q = 0;
constexpr int OFF_K = OFF_Q + 64 * QP;
constexpr int OFF_V = OFF_K + 64 * KP;
constexpr int OFF_P = OFF_V + 64 * KP;
constexpr int ATT_SMEM_FLOATS = OFF_P + 64 * QP;
constexpr int ATT_SMEM_BYTES  = ATT_SMEM_FLOATS * (int)sizeof(float); // 102400

__global__ __launch_bounds__(256, 2) void attn_kernel()
{
    extern __shared__ float sm[];
    float (*QsT)[QP] = (float(*)[QP])(sm + OFF_Q);
    float (*KsT)[KP] = (float(*)[KP])(sm + OFF_K);
    float (*Vs )[KP] = (float(*)[KP])(sm + OFF_V);
    float (*PsT)[QP] = (float(*)[QP])(sm + OFF_P);

    const int qt  = gridDim.x - 1 - blockIdx.x;   // big tiles first
    const int bh  = blockIdx.y;
    const int tid = threadIdx.x;
    const int tx  = tid & 15;     // 4 cols each
    const int ty  = tid >> 4;     // 8 rows each

    const float* Qb = g_Q + (size_t)bh * SEQ * HEAD_DIM;
    const float* Kb = g_K + (size_t)bh * SEQ * HEAD_DIM;
    const float* Vb = g_V + (size_t)bh * SEQ * HEAD_DIM;

    // ---- load Q tile transposed: QsT[e][r] ----
    {
        const int r  = tid >> 1;            // 0..127
        const int e0 = (tid & 1) * 32;      // 0 or 32
        const float* src = Qb + (size_t)(qt * 128 + r) * HEAD_DIM + e0;
#pragma unroll
        for (int j4 = 0; j4 < 8; j4++) {
            float4 v = *(const float4*)(src + 4 * j4);
            QsT[e0 + 4 * j4 + 0][r] = v.x;
            QsT[e0 + 4 * j4 + 1][r] = v.y;
            QsT[e0 + 4 * j4 + 2][r] = v.z;
            QsT[e0 + 4 * j4 + 3][r] = v.w;
        }
    }

    float m_i[8], l_i[8], o[8][4];
#pragma unroll
    for (int i = 0; i < 8; i++) {
        m_i[i] = -1e30f;  l_i[i] = 0.f;
#pragma unroll
        for (int j = 0; j < 4; j++) o[i][j] = 0.f;
    }

    const int n_kt = 2 * qt + 2;
    const int lc = tid >> 2;              // load row/col: 0..63
    const int le0 = (tid & 3) * 16;       // 0..48

    for (int kt = 0; kt < n_kt; kt++) {
        __syncthreads();  // prev PV done before Ks/Vs overwritten (incl. Q on 1st)

        // ---- load K (transposed) and V (natural) tiles ----
        {
            const float* ksrc = Kb + (size_t)(kt * 64 + lc) * HEAD_DIM + le0;
            const float* vsrc = Vb + (size_t)(kt * 64 + lc) * HEAD_DIM + le0;
#pragma unroll
            for (int j4 = 0; j4 < 4; j4++) {
                float4 kv = *(const float4*)(ksrc + 4 * j4);
                KsT[le0 + 4 * j4 + 0][lc] = kv.x;
                KsT[le0 + 4 * j4 + 1][lc] = kv.y;
                KsT[le0 + 4 * j4 + 2][lc] = kv.z;
                KsT[le0 + 4 * j4 + 3][lc] = kv.w;
                *(float4*)&Vs[lc][le0 + 4 * j4] = *(const float4*)(vsrc + 4 * j4);
            }
        }
        __syncthreads();

        // ---- S = Q K^T : acc[8][4] ----
        float acc[8][4];
#pragma unroll
        for (int i = 0; i < 8; i++)
#pragma unroll
            for (int j = 0; j < 4; j++) acc[i][j] = 0.f;

#pragma unroll 8
        for (int kk = 0; kk < 64; kk++) {
            float4 a0 = *(const float4*)&QsT[kk][ty * 8];
            float4 a1 = *(const float4*)&QsT[kk][ty * 8 + 4];
            float4 b  = *(const float4*)&KsT[kk][tx * 4];
            const float a[8] = {a0.x,a0.y,a0.z,a0.w,a1.x,a1.y,a1.z,a1.w};
            const float bb[4] = {b.x,b.y,b.z,b.w};
#pragma unroll
            for (int i = 0; i < 8; i++)
#pragma unroll
                for (int j = 0; j < 4; j++)
                    acc[i][j] += a[i] * bb[j];
        }

        // ---- scale + (diagonal-only) mask ----
        const bool need_mask = (kt >= 2 * qt);   // only the 2 diagonal tiles
#pragma unroll
        for (int i = 0; i < 8; i++)
#pragma unroll
            for (int j = 0; j < 4; j++) {
                float v = acc[i][j] * 0.125f;    // 1/sqrt(64)
                if (need_mask &&
                    (kt * 64 + tx * 4 + j) > (qt * 128 + ty * 8 + i))
                    v = -1e30f;
                acc[i][j] = v;
            }

        // ---- online softmax (row reductions across the 16-lane tx group) ----
#pragma unroll
        for (int i = 0; i < 8; i++) {
            float mr = fmaxf(fmaxf(acc[i][0], acc[i][1]),
                             fmaxf(acc[i][2], acc[i][3]));
            mr = fmaxf(mr, __shfl_xor_sync(0xffffffffu, mr, 1));
            mr = fmaxf(mr, __shfl_xor_sync(0xffffffffu, mr, 2));
            mr = fmaxf(mr, __shfl_xor_sync(0xffffffffu, mr, 4));
            mr = fmaxf(mr, __shfl_xor_sync(0xffffffffu, mr, 8));
            const float mn   = fmaxf(m_i[i], mr);
            const float corr = __expf(m_i[i] - mn);
            m_i[i] = mn;
            float ls = 0.f;
#pragma unroll
            for (int j = 0; j < 4; j++) {
                const float p = __expf(acc[i][j] - mn);
                acc[i][j] = p;
                ls += p;
            }
            ls += __shfl_xor_sync(0xffffffffu, ls, 1);
            ls += __shfl_xor_sync(0xffffffffu, ls, 2);
            ls += __shfl_xor_sync(0xffffffffu, ls, 4);
            ls += __shfl_xor_sync(0xffffffffu, ls, 8);
            l_i[i] = l_i[i] * corr + ls;
#pragma unroll
            for (int j = 0; j < 4; j++) o[i][j] *= corr;
        }

        // ---- store P transposed: PsT[c][r] ----
#pragma unroll
        for (int j = 0; j < 4; j++) {
            *(float4*)&PsT[tx * 4 + j][ty * 8] =
                make_float4(acc[0][j], acc[1][j], acc[2][j], acc[3][j]);
            *(float4*)&PsT[tx * 4 + j][ty * 8 + 4] =
                make_float4(acc[4][j], acc[5][j], acc[6][j], acc[7][j]);
        }
        __syncthreads();

        // ---- O += P V ----
#pragma unroll 8
        for (int cc = 0; cc < 64; cc++) {
            float4 p0 = *(const float4*)&PsT[cc][ty * 8];
            float4 p1 = *(const float4*)&PsT[cc][ty * 8 + 4];
            float4 v  = *(const float4*)&Vs[cc][tx * 4];
            const float p[8] = {p0.x,p0.y,p0.z,p0.w,p1.x,p1.y,p1.z,p1.w};
            const float vv[4] = {v.x,v.y,v.z,v.w};
#pragma unroll
            for (int i = 0; i < 8; i++)
#pragma unroll
                for (int j = 0; j < 4; j++)
                    o[i][j] += p[i] * vv[j];
        }
    }

    // ---- finalize, write context in [B, S, D] layout ----
    const int b = bh >> 4;
    const int h = bh & 15;
#pragma unroll
    for (int i = 0; i < 8; i++) {
        const int qrow = qt * 128 + ty * 8 + i;
        const float inv = 1.f / l_i[i];
        float4 v;
        v.x = o[i][0] * inv;
        v.y = o[i][1] * inv;
        v.z = o[i][2] * inv;
        v.w = o[i][3] * inv;
        float* dst = g_Ctx + ((size_t)(b * SEQ + qrow) * D_MODEL)
                     + h * HEAD_DIM + tx * 4;
        *(float4*)dst = v;
    }
}

// ---------------------------------------------------------------------------
// Kernel 3: output projection (unchanged).
// ---------------------------------------------------------------------------
__global__ __launch_bounds__(256) void oproj_kernel(
    const float* __restrict__ Wo, const float* __restrict__ bo,
    float* __restrict__ out)
{
    __shared__ float AsT[16][128];
    __shared__ float Bs[16][64];

    const int tid = threadIdx.x;
    const int mt  = blockIdx.x;
    const int n0  = blockIdx.y * 64;

    const int m0  = mt * 128;
    const int tx  = tid & 15;
    const int ty  = tid >> 4;

    const int arow = tid & 127;
    const int ac0  = (tid >> 7) * 8;
    const int brow = tid >> 4;
    const int bc0  = (tid & 15) * 4;

    float acc[8][4];
#pragma unroll
    for (int i = 0; i < 8; i++)
#pragma unroll
        for (int j = 0; j < 4; j++) acc[i][j] = 0.f;

    const float* Aptr = g_Ctx + (size_t)(m0 + arow) * D_MODEL + ac0;
    const float* Bptr = Wo + (size_t)brow * D_MODEL + n0 + bc0;

    for (int k0 = 0; k0 < D_MODEL; k0 += 16) {
        float4 a0 = *(const float4*)(Aptr + k0);
        float4 a1 = *(const float4*)(Aptr + k0 + 4);
        float4 b  = *(const float4*)(Bptr + (size_t)k0 * D_MODEL);

        AsT[ac0 + 0][arow] = a0.x;  AsT[ac0 + 1][arow] = a0.y;
        AsT[ac0 + 2][arow] = a0.z;  AsT[ac0 + 3][arow] = a0.w;
        AsT[ac0 + 4][arow] = a1.x;  AsT[ac0 + 5][arow] = a1.y;
        AsT[ac0 + 6][arow] = a1.z;  AsT[ac0 + 7][arow] = a1.w;
        *(float4*)&Bs[brow][bc0] = b;
        __syncthreads();

#pragma unroll
        for (int kk = 0; kk < 16; kk++) {
            float a[8], bb[4];
#pragma unroll
            for (int i = 0; i < 8; i++) a[i] = AsT[kk][ty * 8 + i];
#pragma unroll
            for (int j = 0; j < 4; j++) bb[j] = Bs[kk][tx * 4 + j];
#pragma unroll
            for (int i = 0; i < 8; i++)
#pragma unroll
                for (int j = 0; j < 4; j++)
                    acc[i][j] += a[i] * bb[j];
        }
        __syncthreads();
    }

    float bv4[4];
#pragma unroll
    for (int j = 0; j < 4; j++) bv4[j] = bo[n0 + tx * 4 + j];

#pragma unroll
    for (int i = 0; i < 8; i++) {
        const int m = m0 + ty * 8 + i;
        float4 v;
        v.x = acc[i][0] + bv4[0];
        v.y = acc[i][1] + bv4[1];
        v.z = acc[i][2] + bv4[2];
        v.w = acc[i][3] + bv4[3];
        *(float4*)(out + (size_t)m * D_MODEL + n0 + tx * 4) = v;
    }
}

// ---------------------------------------------------------------------------
// kernel_launch — graph-capturable, allocation-free.
// Inputs: hidden_state, Wq, Wk, Wv, bq, bk, bv, Wo, bo
// ---------------------------------------------------------------------------
extern "C" void kernel_launch(void* const* d_in, const int* in_sizes, int n_in,
                              void* d_out, int out_size)
{
    const float* X  = (const float*)d_in[0];
    const float* Wq = (const float*)d_in[1];
    const float* Wk = (const float*)d_in[2];
    const float* Wv = (const float*)d_in[3];
    const float* bq = (const float*)d_in[4];
    const float* bk = (const float*)d_in[5];
    const float* bv = (const float*)d_in[6];
    const float* Wo = (const float*)d_in[7];
    const float* bo = (const float*)d_in[8];
    float* out = (float*)d_out;

    cudaFuncSetAttribute(attn_kernel,
                         cudaFuncAttributeMaxDynamicSharedMemorySize,
                         ATT_SMEM_BYTES);

    // 1) QKV projections
    {
        dim3 grid(MROWS / 128, 3 * N_HEADS);
        qkv_kernel<<<grid, 256>>>(X, Wq, Wk, Wv, bq, bk, bv);
    }
    // 2) causal flash attention
    {
        dim3 grid(SEQ / 128, BATCH * N_HEADS);
        attn_kernel<<<grid, 256, ATT_SMEM_BYTES>>>();
    }
    // 3) output projection
    {
        dim3 grid(MROWS / 128, D_MODEL / 64);
        oproj_kernel<<<grid, 256>>>(Wo, bo, out);
    }
}

// round 8
// speedup vs baseline: 2.8203x; 1.0067x over previous
#include <cuda_runtime.h>
#include <cuda_bf16.h>
#include <math.h>

// Problem constants
constexpr int BATCH    = 2;
constexpr int SEQ      = 2048;
constexpr int D_MODEL  = 1024;
constexpr int N_HEADS  = 16;
constexpr int HEAD_DIM = 64;
constexpr int MROWS    = BATCH * SEQ;   // 4096

// ---------------------------------------------------------------------------
// Device scratch (allocations are forbidden; use __device__ globals)
// ---------------------------------------------------------------------------
__device__ float g_Q[BATCH * N_HEADS * SEQ * HEAD_DIM];   // [B,H,S,hd]
__device__ float g_K[BATCH * N_HEADS * SEQ * HEAD_DIM];
__device__ float g_V[BATCH * N_HEADS * SEQ * HEAD_DIM];
__device__ float g_Ctx[BATCH * SEQ * D_MODEL];            // [B,S,D]

// ---------------------------------------------------------------------------
// Kernel 1: fused QKV projection (unchanged from round 1).
// ---------------------------------------------------------------------------
__global__ __launch_bounds__(256) void qkv_kernel(
    const float* __restrict__ X,
    const float* __restrict__ Wq, const float* __restrict__ Wk, const float* __restrict__ Wv,
    const float* __restrict__ bq, const float* __restrict__ bk, const float* __restrict__ bv)
{
    __shared__ float AsT[16][128];
    __shared__ float Bs[16][64];

    const int tid = threadIdx.x;
    const int mt  = blockIdx.x;
    const int yy  = blockIdx.y;
    const int mat = yy >> 4;
    const int h   = yy & 15;

    const float* W;  const float* bias;  float* Out;
    if (mat == 0)      { W = Wq; bias = bq; Out = g_Q; }
    else if (mat == 1) { W = Wk; bias = bk; Out = g_K; }
    else               { W = Wv; bias = bv; Out = g_V; }
    W    += h * D_MODEL * HEAD_DIM;
    bias += h * HEAD_DIM;

    const int m0  = mt * 128;
    const int tx  = tid & 15;
    const int ty  = tid >> 4;

    const int arow = tid & 127;
    const int ac0  = (tid >> 7) * 8;
    const int brow = tid >> 4;
    const int bc0  = (tid & 15) * 4;

    float acc[8][4];
#pragma unroll
    for (int i = 0; i < 8; i++)
#pragma unroll
        for (int j = 0; j < 4; j++) acc[i][j] = 0.f;

    const float* Aptr = X + (size_t)(m0 + arow) * D_MODEL + ac0;
    const float* Bptr = W + brow * HEAD_DIM + bc0;

    for (int k0 = 0; k0 < D_MODEL; k0 += 16) {
        float4 a0 = *(const float4*)(Aptr + k0);
        float4 a1 = *(const float4*)(Aptr + k0 + 4);
        float4 b  = *(const float4*)(Bptr + (size_t)k0 * HEAD_DIM);

        AsT[ac0 + 0][arow] = a0.x;  AsT[ac0 + 1][arow] = a0.y;
        AsT[ac0 + 2][arow] = a0.z;  AsT[ac0 + 3][arow] = a0.w;
        AsT[ac0 + 4][arow] = a1.x;  AsT[ac0 + 5][arow] = a1.y;
        AsT[ac0 + 6][arow] = a1.z;  AsT[ac0 + 7][arow] = a1.w;
        *(float4*)&Bs[brow][bc0] = b;
        __syncthreads();

#pragma unroll
        for (int kk = 0; kk < 16; kk++) {
            float a[8], bb[4];
#pragma unroll
            for (int i = 0; i < 8; i++) a[i] = AsT[kk][ty * 8 + i];
#pragma unroll
            for (int j = 0; j < 4; j++) bb[j] = Bs[kk][tx * 4 + j];
#pragma unroll
            for (int i = 0; i < 8; i++)
#pragma unroll
                for (int j = 0; j < 4; j++)
                    acc[i][j] += a[i] * bb[j];
        }
        __syncthreads();
    }

    float bv4[4];
#pragma unroll
    for (int j = 0; j < 4; j++) bv4[j] = bias[tx * 4 + j];

#pragma unroll
    for (int i = 0; i < 8; i++) {
        const int m = m0 + ty * 8 + i;
        const int b = m >> 11;
        const int s = m & 2047;
        float4 v;
        v.x = acc[i][0] + bv4[0];
        v.y = acc[i][1] + bv4[1];
        v.z = acc[i][2] + bv4[2];
        v.w = acc[i][3] + bv4[3];
        float* dst = Out + (((size_t)(b * N_HEADS + h) * SEQ + s) * HEAD_DIM) + tx * 4;
        *(float4*)dst = v;
    }
}

// ---------------------------------------------------------------------------
// Kernel 2: causal flash attention, register-tiled fp32.
// Br=128 query rows per block, Bc=64 keys per tile. 256 threads.
// ---------------------------------------------------------------------------
constexpr int QP = 132;   // pitch for [e][r] / [c][r] arrays (r-dim 128 + pad)
constexpr int KP = 68;    // pitch for [e][c] / [c][e] arrays (64 + pad)

constexpr int OFF_Q = 0;
constexpr int OFF_K = OFF_Q + 64 * QP;
constexpr int OFF_V = OFF_K + 64 * KP;
constexpr int OFF_P = OFF_V + 64 * KP;
constexpr int ATT_SMEM_FLOATS = OFF_P + 64 * QP;
constexpr int ATT_SMEM_BYTES  = ATT_SMEM_FLOATS * (int)sizeof(float); // 102400

__global__ __launch_bounds__(256, 2) void attn_kernel()
{
    extern __shared__ float sm[];
    float (*QsT)[QP] = (float(*)[QP])(sm + OFF_Q);
    float (*KsT)[KP] = (float(*)[KP])(sm + OFF_K);
    float (*Vs )[KP] = (float(*)[KP])(sm + OFF_V);
    float (*PsT)[QP] = (float(*)[QP])(sm + OFF_P);

    const int qt  = gridDim.x - 1 - blockIdx.x;   // big tiles first
    const int bh  = blockIdx.y;
    const int tid = threadIdx.x;
    const int tx  = tid & 15;     // 4 cols each
    const int ty  = tid >> 4;     // 8 rows each

    const float* Qb = g_Q + (size_t)bh * SEQ * HEAD_DIM;
    const float* Kb = g_K + (size_t)bh * SEQ * HEAD_DIM;
    const float* Vb = g_V + (size_t)bh * SEQ * HEAD_DIM;

    // ---- load Q tile transposed: QsT[e][r] ----
    {
        const int r  = tid >> 1;            // 0..127
        const int e0 = (tid & 1) * 32;      // 0 or 32
        const float* src = Qb + (size_t)(qt * 128 + r) * HEAD_DIM + e0;
#pragma unroll
        for (int j4 = 0; j4 < 8; j4++) {
            float4 v = *(const float4*)(src + 4 * j4);
            QsT[e0 + 4 * j4 + 0][r] = v.x;
            QsT[e0 + 4 * j4 + 1][r] = v.y;
            QsT[e0 + 4 * j4 + 2][r] = v.z;
            QsT[e0 + 4 * j4 + 3][r] = v.w;
        }
    }

    float m_i[8], l_i[8], o[8][4];
#pragma unroll
    for (int i = 0; i < 8; i++) {
        m_i[i] = -1e30f;  l_i[i] = 0.f;
#pragma unroll
        for (int j = 0; j < 4; j++) o[i][j] = 0.f;
    }

    const int n_kt = 2 * qt + 2;
    const int lc = tid >> 2;              // load row/col: 0..63
    const int le0 = (tid & 3) * 16;       // 0..48

    for (int kt = 0; kt < n_kt; kt++) {
        __syncthreads();  // prev PV done before Ks/Vs overwritten (incl. Q on 1st)

        // ---- load K (transposed) and V (natural) tiles ----
        {
            const float* ksrc = Kb + (size_t)(kt * 64 + lc) * HEAD_DIM + le0;
            const float* vsrc = Vb + (size_t)(kt * 64 + lc) * HEAD_DIM + le0;
#pragma unroll
            for (int j4 = 0; j4 < 4; j4++) {
                float4 kv = *(const float4*)(ksrc + 4 * j4);
                KsT[le0 + 4 * j4 + 0][lc] = kv.x;
                KsT[le0 + 4 * j4 + 1][lc] = kv.y;
                KsT[le0 + 4 * j4 + 2][lc] = kv.z;
                KsT[le0 + 4 * j4 + 3][lc] = kv.w;
                *(float4*)&Vs[lc][le0 + 4 * j4] = *(const float4*)(vsrc + 4 * j4);
            }
        }
        __syncthreads();

        // ---- S = Q K^T : acc[8][4] ----
        float acc[8][4];
#pragma unroll
        for (int i = 0; i < 8; i++)
#pragma unroll
            for (int j = 0; j < 4; j++) acc[i][j] = 0.f;

#pragma unroll 8
        for (int kk = 0; kk < 64; kk++) {
            float4 a0 = *(const float4*)&QsT[kk][ty * 8];
            float4 a1 = *(const float4*)&QsT[kk][ty * 8 + 4];
            float4 b  = *(const float4*)&KsT[kk][tx * 4];
            const float a[8] = {a0.x,a0.y,a0.z,a0.w,a1.x,a1.y,a1.z,a1.w};
            const float bb[4] = {b.x,b.y,b.z,b.w};
#pragma unroll
            for (int i = 0; i < 8; i++)
#pragma unroll
                for (int j = 0; j < 4; j++)
                    acc[i][j] += a[i] * bb[j];
        }

        // ---- scale + (diagonal-only) mask ----
        const bool need_mask = (kt >= 2 * qt);   // only the 2 diagonal tiles
#pragma unroll
        for (int i = 0; i < 8; i++)
#pragma unroll
            for (int j = 0; j < 4; j++) {
                float v = acc[i][j] * 0.125f;    // 1/sqrt(64)
                if (need_mask &&
                    (kt * 64 + tx * 4 + j) > (qt * 128 + ty * 8 + i))
                    v = -1e30f;
                acc[i][j] = v;
            }

        // ---- online softmax (row reductions across the 16-lane tx group) ----
#pragma unroll
        for (int i = 0; i < 8; i++) {
            float mr = fmaxf(fmaxf(acc[i][0], acc[i][1]),
                             fmaxf(acc[i][2], acc[i][3]));
            mr = fmaxf(mr, __shfl_xor_sync(0xffffffffu, mr, 1));
            mr = fmaxf(mr, __shfl_xor_sync(0xffffffffu, mr, 2));
            mr = fmaxf(mr, __shfl_xor_sync(0xffffffffu, mr, 4));
            mr = fmaxf(mr, __shfl_xor_sync(0xffffffffu, mr, 8));
            const float mn   = fmaxf(m_i[i], mr);
            const float corr = __expf(m_i[i] - mn);
            m_i[i] = mn;
            float ls = 0.f;
#pragma unroll
            for (int j = 0; j < 4; j++) {
                const float p = __expf(acc[i][j] - mn);
                acc[i][j] = p;
                ls += p;
            }
            ls += __shfl_xor_sync(0xffffffffu, ls, 1);
            ls += __shfl_xor_sync(0xffffffffu, ls, 2);
            ls += __shfl_xor_sync(0xffffffffu, ls, 4);
            ls += __shfl_xor_sync(0xffffffffu, ls, 8);
            l_i[i] = l_i[i] * corr + ls;
#pragma unroll
            for (int j = 0; j < 4; j++) o[i][j] *= corr;
        }

        // ---- store P transposed: PsT[c][r] ----
#pragma unroll
        for (int j = 0; j < 4; j++) {
            *(float4*)&PsT[tx * 4 + j][ty * 8] =
                make_float4(acc[0][j], acc[1][j], acc[2][j], acc[3][j]);
            *(float4*)&PsT[tx * 4 + j][ty * 8 + 4] =
                make_float4(acc[4][j], acc[5][j], acc[6][j], acc[7][j]);
        }
        __syncthreads();

        // ---- O += P V ----
#pragma unroll 8
        for (int cc = 0; cc < 64; cc++) {
            float4 p0 = *(const float4*)&PsT[cc][ty * 8];
            float4 p1 = *(const float4*)&PsT[cc][ty * 8 + 4];
            float4 v  = *(const float4*)&Vs[cc][tx * 4];
            const float p[8] = {p0.x,p0.y,p0.z,p0.w,p1.x,p1.y,p1.z,p1.w};
            const float vv[4] = {v.x,v.y,v.z,v.w};
#pragma unroll
            for (int i = 0; i < 8; i++)
#pragma unroll
                for (int j = 0; j < 4; j++)
                    o[i][j] += p[i] * vv[j];
        }
    }

    // ---- finalize, write context in [B, S, D] layout ----
    const int b = bh >> 4;
    const int h = bh & 15;
#pragma unroll
    for (int i = 0; i < 8; i++) {
        const int qrow = qt * 128 + ty * 8 + i;
        const float inv = 1.f / l_i[i];
        float4 v;
        v.x = o[i][0] * inv;
        v.y = o[i][1] * inv;
        v.z = o[i][2] * inv;
        v.w = o[i][3] * inv;
        float* dst = g_Ctx + ((size_t)(b * SEQ + qrow) * D_MODEL)
                     + h * HEAD_DIM + tx * 4;
        *(float4*)dst = v;
    }
}

// ---------------------------------------------------------------------------
// Kernel 3: output projection (unchanged).
// ---------------------------------------------------------------------------
__global__ __launch_bounds__(256) void oproj_kernel(
    const float* __restrict__ Wo, const float* __restrict__ bo,
    float* __restrict__ out)
{
    __shared__ float AsT[16][128];
    __shared__ float Bs[16][64];

    const int tid = threadIdx.x;
    const int mt  = blockIdx.x;
    const int n0  = blockIdx.y * 64;

    const int m0  = mt * 128;
    const int tx  = tid & 15;
    const int ty  = tid >> 4;

    const int arow = tid & 127;
    const int ac0  = (tid >> 7) * 8;
    const int brow = tid >> 4;
    const int bc0  = (tid & 15) * 4;

    float acc[8][4];
#pragma unroll
    for (int i = 0; i < 8; i++)
#pragma unroll
        for (int j = 0; j < 4; j++) acc[i][j] = 0.f;

    const float* Aptr = g_Ctx + (size_t)(m0 + arow) * D_MODEL + ac0;
    const float* Bptr = Wo + (size_t)brow * D_MODEL + n0 + bc0;

    for (int k0 = 0; k0 < D_MODEL; k0 += 16) {
        float4 a0 = *(const float4*)(Aptr + k0);
        float4 a1 = *(const float4*)(Aptr + k0 + 4);
        float4 b  = *(const float4*)(Bptr + (size_t)k0 * D_MODEL);

        AsT[ac0 + 0][arow] = a0.x;  AsT[ac0 + 1][arow] = a0.y;
        AsT[ac0 + 2][arow] = a0.z;  AsT[ac0 + 3][arow] = a0.w;
        AsT[ac0 + 4][arow] = a1.x;  AsT[ac0 + 5][arow] = a1.y;
        AsT[ac0 + 6][arow] = a1.z;  AsT[ac0 + 7][arow] = a1.w;
        *(float4*)&Bs[brow][bc0] = b;
        __syncthreads();

#pragma unroll
        for (int kk = 0; kk < 16; kk++) {
            float a[8], bb[4];
#pragma unroll
            for (int i = 0; i < 8; i++) a[i] = AsT[kk][ty * 8 + i];
#pragma unroll
            for (int j = 0; j < 4; j++) bb[j] = Bs[kk][tx * 4 + j];
#pragma unroll
            for (int i = 0; i < 8; i++)
#pragma unroll
                for (int j = 0; j < 4; j++)
                    acc[i][j] += a[i] * bb[j];
        }
        __syncthreads();
    }

    float bv4[4];
#pragma unroll
    for (int j = 0; j < 4; j++) bv4[j] = bo[n0 + tx * 4 + j];

#pragma unroll
    for (int i = 0; i < 8; i++) {
        const int m = m0 + ty * 8 + i;
        float4 v;
        v.x = acc[i][0] + bv4[0];
        v.y = acc[i][1] + bv4[1];
        v.z = acc[i][2] + bv4[2];
        v.w = acc[i][3] + bv4[3];
        *(float4*)(out + (size_t)m * D_MODEL + n0 + tx * 4) = v;
    }
}

// ---------------------------------------------------------------------------
// kernel_launch — graph-capturable, allocation-free.
// Inputs: hidden_state, Wq, Wk, Wv, bq, bk, bv, Wo, bo
// ---------------------------------------------------------------------------
extern "C" void kernel_launch(void* const* d_in, const int* in_sizes, int n_in,
                              void* d_out, int out_size)
{
    const float* X  = (const float*)d_in[0];
    const float* Wq = (const float*)d_in[1];
    const float* Wk = (const float*)d_in[2];
    const float* Wv = (const float*)d_in[3];
    const float* bq = (const float*)d_in[4];
    const float* bk = (const float*)d_in[5];
    const float* bv = (const float*)d_in[6];
    const float* Wo = (const float*)d_in[7];
    const float* bo = (const float*)d_in[8];
    float* out = (float*)d_out;

    cudaFuncSetAttribute(attn_kernel,
                         cudaFuncAttributeMaxDynamicSharedMemorySize,
                         ATT_SMEM_BYTES);

    // 1) QKV projections
    {
        dim3 grid(MROWS / 128, 3 * N_HEADS);
        qkv_kernel<<<grid, 256>>>(X, Wq, Wk, Wv, bq, bk, bv);
    }
    // 2) causal flash attention
    {
        dim3 grid(SEQ / 128, BATCH * N_HEADS);
        attn_kernel<<<grid, 256, ATT_SMEM_BYTES>>>();
    }
    // 3) output projection
    {
        dim3 grid(MROWS / 128, D_MODEL / 64);
        oproj_kernel<<<grid, 256>>>(Wo, bo, out);
    }
}

// round 9
// speedup vs baseline: 2.9883x; 1.0596x over previous
#include <cuda_runtime.h>
#include <cuda_bf16.h>
#include <math.h>

// Problem constants
constexpr int BATCH    = 2;
constexpr int SEQ      = 2048;
constexpr int D_MODEL  = 1024;
constexpr int N_HEADS  = 16;
constexpr int HEAD_DIM = 64;
constexpr int MROWS    = BATCH * SEQ;   // 4096

// ---------------------------------------------------------------------------
// Device scratch (allocations are forbidden; use __device__ globals)
// ---------------------------------------------------------------------------
__device__ float g_Q[BATCH * N_HEADS * SEQ * HEAD_DIM];   // [B,H,S,hd]
__device__ float g_K[BATCH * N_HEADS * SEQ * HEAD_DIM];
__device__ float g_V[BATCH * N_HEADS * SEQ * HEAD_DIM];
__device__ float g_Ctx[BATCH * SEQ * D_MODEL];            // [B,S,D]

// ---------------------------------------------------------------------------
// Kernel 1: fused QKV projection, 128x128 tile (head PAIR per block).
// grid = (32, 24): y -> mat = y/8, head pair h0 = 2*(y%8).
// 256 threads, 8x8 microtile split 4+4 at offset 64 (rows ty*4 / 64+ty*4,
// cols tx*4 / 64+tx*4). Loop skeleton identical to the round-2 kernel
// (load -> sync -> fma -> sync, no register prefetch, no templates).
// ---------------------------------------------------------------------------
__global__ __launch_bounds__(256) void qkv_kernel(
    const float* __restrict__ X,
    const float* __restrict__ Wq, const float* __restrict__ Wk, const float* __restrict__ Wv,
    const float* __restrict__ bq, const float* __restrict__ bk, const float* __restrict__ bv)
{
    __shared__ float AsT[16][128];   // [k][m]
    __shared__ float Bs[16][132];    // [k][n], padded pitch

    const int tid = threadIdx.x;
    const int yy  = blockIdx.y;
    const int mat = yy >> 3;
    const int h0  = (yy & 7) * 2;

    const float* W;  const float* bias;  float* Out;
    if (mat == 0)      { W = Wq; bias = bq; Out = g_Q; }
    else if (mat == 1) { W = Wk; bias = bk; Out = g_K; }
    else               { W = Wv; bias = bv; Out = g_V; }

    const int m0 = blockIdx.x * 128;
    const int tx = tid & 15;
    const int ty = tid >> 4;

    // load mappings
    const int arow = tid & 127;          // 0..127
    const int ac0  = (tid >> 7) * 8;     // 0 or 8
    const int brow = tid >> 4;           // 0..15 (k row)
    const int bc0  = (tid & 15) * 8;     // 0..120 (8-wide col group)

    const float* Aptr = X + (size_t)(m0 + arow) * D_MODEL + ac0;
    // B col n -> head h0 + (n>>6), elem n&63; an 8-wide group stays in one head
    const int bhead = h0 + (bc0 >> 6);
    const int be0   = bc0 & 63;
    const float* Bptr = W + ((size_t)bhead * D_MODEL + brow) * HEAD_DIM + be0;

    float acc[8][8];
#pragma unroll
    for (int i = 0; i < 8; i++)
#pragma unroll
        for (int j = 0; j < 8; j++) acc[i][j] = 0.f;

    for (int k0 = 0; k0 < D_MODEL; k0 += 16) {
        float4 a0 = *(const float4*)(Aptr + k0);
        float4 a1 = *(const float4*)(Aptr + k0 + 4);
        float4 b0 = *(const float4*)(Bptr + (size_t)k0 * HEAD_DIM);
        float4 b1 = *(const float4*)(Bptr + (size_t)k0 * HEAD_DIM + 4);

        AsT[ac0 + 0][arow] = a0.x;  AsT[ac0 + 1][arow] = a0.y;
        AsT[ac0 + 2][arow] = a0.z;  AsT[ac0 + 3][arow] = a0.w;
        AsT[ac0 + 4][arow] = a1.x;  AsT[ac0 + 5][arow] = a1.y;
        AsT[ac0 + 6][arow] = a1.z;  AsT[ac0 + 7][arow] = a1.w;
        *(float4*)&Bs[brow][bc0]     = b0;
        *(float4*)&Bs[brow][bc0 + 4] = b1;
        __syncthreads();

#pragma unroll
        for (int kk = 0; kk < 16; kk++) {
            float4 qa0 = *(const float4*)&AsT[kk][ty * 4];
            float4 qa1 = *(const float4*)&AsT[kk][64 + ty * 4];
            float4 qb0 = *(const float4*)&Bs[kk][tx * 4];
            float4 qb1 = *(const float4*)&Bs[kk][64 + tx * 4];
            const float a[8] = {qa0.x,qa0.y,qa0.z,qa0.w,qa1.x,qa1.y,qa1.z,qa1.w};
            const float b[8] = {qb0.x,qb0.y,qb0.z,qb0.w,qb1.x,qb1.y,qb1.z,qb1.w};
#pragma unroll
            for (int i = 0; i < 8; i++)
#pragma unroll
                for (int j = 0; j < 8; j++)
                    acc[i][j] += a[i] * b[j];
        }
        __syncthreads();
    }

    // ---- epilogue: bias + scatter to [B,H,S,hd] ----
#pragma unroll
    for (int jb = 0; jb < 2; jb++) {
        const int head = h0 + jb;
        const float4 bv4 = *(const float4*)(bias + head * HEAD_DIM + tx * 4);
#pragma unroll
        for (int ib = 0; ib < 2; ib++) {
#pragma unroll
            for (int i = 0; i < 4; i++) {
                const int m = m0 + ib * 64 + ty * 4 + i;
                const int b = m >> 11;
                const int s = m & 2047;
                float4 v;
                v.x = acc[ib * 4 + i][jb * 4 + 0] + bv4.x;
                v.y = acc[ib * 4 + i][jb * 4 + 1] + bv4.y;
                v.z = acc[ib * 4 + i][jb * 4 + 2] + bv4.z;
                v.w = acc[ib * 4 + i][jb * 4 + 3] + bv4.w;
                float* dst = Out +
                    (((size_t)(b * N_HEADS + head) * SEQ + s) * HEAD_DIM) + tx * 4;
                *(float4*)dst = v;
            }
        }
    }
}

// ---------------------------------------------------------------------------
// Kernel 2: causal flash attention (unchanged, known-passing).
// ---------------------------------------------------------------------------
constexpr int QP = 132;
constexpr int KP = 68;
constexpr int OFF_Q = 0;
constexpr int OFF_K = OFF_Q + 64 * QP;
constexpr int OFF_V = OFF_K + 64 * KP;
constexpr int OFF_P = OFF_V + 64 * KP;
constexpr int ATT_SMEM_FLOATS = OFF_P + 64 * QP;
constexpr int ATT_SMEM_BYTES  = ATT_SMEM_FLOATS * (int)sizeof(float); // 102400

__global__ __launch_bounds__(256, 2) void attn_kernel()
{
    extern __shared__ float sm[];
    float (*QsT)[QP] = (float(*)[QP])(sm + OFF_Q);
    float (*KsT)[KP] = (float(*)[KP])(sm + OFF_K);
    float (*Vs )[KP] = (float(*)[KP])(sm + OFF_V);
    float (*PsT)[QP] = (float(*)[QP])(sm + OFF_P);

    const int qt  = gridDim.x - 1 - blockIdx.x;
    const int bh  = blockIdx.y;
    const int tid = threadIdx.x;
    const int tx  = tid & 15;
    const int ty  = tid >> 4;

    const float* Qb = g_Q + (size_t)bh * SEQ * HEAD_DIM;
    const float* Kb = g_K + (size_t)bh * SEQ * HEAD_DIM;
    const float* Vb = g_V + (size_t)bh * SEQ * HEAD_DIM;

    {
        const int r  = tid >> 1;
        const int e0 = (tid & 1) * 32;
        const float* src = Qb + (size_t)(qt * 128 + r) * HEAD_DIM + e0;
#pragma unroll
        for (int j4 = 0; j4 < 8; j4++) {
            float4 v = *(const float4*)(src + 4 * j4);
            QsT[e0 + 4 * j4 + 0][r] = v.x;
            QsT[e0 + 4 * j4 + 1][r] = v.y;
            QsT[e0 + 4 * j4 + 2][r] = v.z;
            QsT[e0 + 4 * j4 + 3][r] = v.w;
        }
    }

    float m_i[8], l_i[8], o[8][4];
#pragma unroll
    for (int i = 0; i < 8; i++) {
        m_i[i] = -1e30f;  l_i[i] = 0.f;
#pragma unroll
        for (int j = 0; j < 4; j++) o[i][j] = 0.f;
    }

    const int n_kt = 2 * qt + 2;
    const int lc  = tid >> 2;
    const int le0 = (tid & 3) * 16;

    for (int kt = 0; kt < n_kt; kt++) {
        __syncthreads();
        {
            const float* ksrc = Kb + (size_t)(kt * 64 + lc) * HEAD_DIM + le0;
            const float* vsrc = Vb + (size_t)(kt * 64 + lc) * HEAD_DIM + le0;
#pragma unroll
            for (int j4 = 0; j4 < 4; j4++) {
                float4 kv = *(const float4*)(ksrc + 4 * j4);
                KsT[le0 + 4 * j4 + 0][lc] = kv.x;
                KsT[le0 + 4 * j4 + 1][lc] = kv.y;
                KsT[le0 + 4 * j4 + 2][lc] = kv.z;
                KsT[le0 + 4 * j4 + 3][lc] = kv.w;
                *(float4*)&Vs[lc][le0 + 4 * j4] = *(const float4*)(vsrc + 4 * j4);
            }
        }
        __syncthreads();

        float acc[8][4];
#pragma unroll
        for (int i = 0; i < 8; i++)
#pragma unroll
            for (int j = 0; j < 4; j++) acc[i][j] = 0.f;

#pragma unroll 8
        for (int kk = 0; kk < 64; kk++) {
            float4 a0 = *(const float4*)&QsT[kk][ty * 8];
            float4 a1 = *(const float4*)&QsT[kk][ty * 8 + 4];
            float4 b  = *(const float4*)&KsT[kk][tx * 4];
            const float a[8] = {a0.x,a0.y,a0.z,a0.w,a1.x,a1.y,a1.z,a1.w};
            const float bb[4] = {b.x,b.y,b.z,b.w};
#pragma unroll
            for (int i = 0; i < 8; i++)
#pragma unroll
                for (int j = 0; j < 4; j++)
                    acc[i][j] += a[i] * bb[j];
        }

        const bool need_mask = (kt >= 2 * qt);
#pragma unroll
        for (int i = 0; i < 8; i++)
#pragma unroll
            for (int j = 0; j < 4; j++) {
                float v = acc[i][j] * 0.125f;
                if (need_mask &&
                    (kt * 64 + tx * 4 + j) > (qt * 128 + ty * 8 + i))
                    v = -1e30f;
                acc[i][j] = v;
            }

#pragma unroll
        for (int i = 0; i < 8; i++) {
            float mr = fmaxf(fmaxf(acc[i][0], acc[i][1]),
                             fmaxf(acc[i][2], acc[i][3]));
            mr = fmaxf(mr, __shfl_xor_sync(0xffffffffu, mr, 1));
            mr = fmaxf(mr, __shfl_xor_sync(0xffffffffu, mr, 2));
            mr = fmaxf(mr, __shfl_xor_sync(0xffffffffu, mr, 4));
            mr = fmaxf(mr, __shfl_xor_sync(0xffffffffu, mr, 8));
            const float mn   = fmaxf(m_i[i], mr);
            const float corr = __expf(m_i[i] - mn);
            m_i[i] = mn;
            float ls = 0.f;
#pragma unroll
            for (int j = 0; j < 4; j++) {
                const float p = __expf(acc[i][j] - mn);
                acc[i][j] = p;
                ls += p;
            }
            ls += __shfl_xor_sync(0xffffffffu, ls, 1);
            ls += __shfl_xor_sync(0xffffffffu, ls, 2);
            ls += __shfl_xor_sync(0xffffffffu, ls, 4);
            ls += __shfl_xor_sync(0xffffffffu, ls, 8);
            l_i[i] = l_i[i] * corr + ls;
#pragma unroll
            for (int j = 0; j < 4; j++) o[i][j] *= corr;
        }

#pragma unroll
        for (int j = 0; j < 4; j++) {
            *(float4*)&PsT[tx * 4 + j][ty * 8] =
                make_float4(acc[0][j], acc[1][j], acc[2][j], acc[3][j]);
            *(float4*)&PsT[tx * 4 + j][ty * 8 + 4] =
                make_float4(acc[4][j], acc[5][j], acc[6][j], acc[7][j]);
        }
        __syncthreads();

#pragma unroll 8
        for (int cc = 0; cc < 64; cc++) {
            float4 p0 = *(const float4*)&PsT[cc][ty * 8];
            float4 p1 = *(const float4*)&PsT[cc][ty * 8 + 4];
            float4 v  = *(const float4*)&Vs[cc][tx * 4];
            const float p[8] = {p0.x,p0.y,p0.z,p0.w,p1.x,p1.y,p1.z,p1.w};
            const float vv[4] = {v.x,v.y,v.z,v.w};
#pragma unroll
            for (int i = 0; i < 8; i++)
#pragma unroll
                for (int j = 0; j < 4; j++)
                    o[i][j] += p[i] * vv[j];
        }
    }

    const int b = bh >> 4;
    const int h = bh & 15;
#pragma unroll
    for (int i = 0; i < 8; i++) {
        const int qrow = qt * 128 + ty * 8 + i;
        const float inv = 1.f / l_i[i];
        float4 v;
        v.x = o[i][0] * inv;
        v.y = o[i][1] * inv;
        v.z = o[i][2] * inv;
        v.w = o[i][3] * inv;
        float* dst = g_Ctx + ((size_t)(b * SEQ + qrow) * D_MODEL)
                     + h * HEAD_DIM + tx * 4;
        *(float4*)dst = v;
    }
}

// ---------------------------------------------------------------------------
// Kernel 3: output projection, 128x128 tile. grid = (32, 8).
// Same microkernel as qkv_kernel; plain row-major B and output.
// ---------------------------------------------------------------------------
__global__ __launch_bounds__(256) void oproj_kernel(
    const float* __restrict__ Wo, const float* __restrict__ bo,
    float* __restrict__ out)
{
    __shared__ float AsT[16][128];
    __shared__ float Bs[16][132];

    const int tid = threadIdx.x;
    const int m0  = blockIdx.x * 128;
    const int n0  = blockIdx.y * 128;
    const int tx  = tid & 15;
    const int ty  = tid >> 4;

    const int arow = tid & 127;
    const int ac0  = (tid >> 7) * 8;
    const int brow = tid >> 4;
    const int bc0  = (tid & 15) * 8;

    const float* Aptr = g_Ctx + (size_t)(m0 + arow) * D_MODEL + ac0;
    const float* Bptr = Wo + (size_t)brow * D_MODEL + n0 + bc0;

    float acc[8][8];
#pragma unroll
    for (int i = 0; i < 8; i++)
#pragma unroll
        for (int j = 0; j < 8; j++) acc[i][j] = 0.f;

    for (int k0 = 0; k0 < D_MODEL; k0 += 16) {
        float4 a0 = *(const float4*)(Aptr + k0);
        float4 a1 = *(const float4*)(Aptr + k0 + 4);
        float4 b0 = *(const float4*)(Bptr + (size_t)k0 * D_MODEL);
        float4 b1 = *(const float4*)(Bptr + (size_t)k0 * D_MODEL + 4);

        AsT[ac0 + 0][arow] = a0.x;  AsT[ac0 + 1][arow] = a0.y;
        AsT[ac0 + 2][arow] = a0.z;  AsT[ac0 + 3][arow] = a0.w;
        AsT[ac0 + 4][arow] = a1.x;  AsT[ac0 + 5][arow] = a1.y;
        AsT[ac0 + 6][arow] = a1.z;  AsT[ac0 + 7][arow] = a1.w;
        *(float4*)&Bs[brow][bc0]     = b0;
        *(float4*)&Bs[brow][bc0 + 4] = b1;
        __syncthreads();

#pragma unroll
        for (int kk = 0; kk < 16; kk++) {
            float4 qa0 = *(const float4*)&AsT[kk][ty * 4];
            float4 qa1 = *(const float4*)&AsT[kk][64 + ty * 4];
            float4 qb0 = *(const float4*)&Bs[kk][tx * 4];
            float4 qb1 = *(const float4*)&Bs[kk][64 + tx * 4];
            const float a[8] = {qa0.x,qa0.y,qa0.z,qa0.w,qa1.x,qa1.y,qa1.z,qa1.w};
            const float b[8] = {qb0.x,qb0.y,qb0.z,qb0.w,qb1.x,qb1.y,qb1.z,qb1.w};
#pragma unroll
            for (int i = 0; i < 8; i++)
#pragma unroll
                for (int j = 0; j < 8; j++)
                    acc[i][j] += a[i] * b[j];
        }
        __syncthreads();
    }

#pragma unroll
    for (int jb = 0; jb < 2; jb++) {
        const float4 bv4 = *(const float4*)(bo + n0 + jb * 64 + tx * 4);
#pragma unroll
        for (int ib = 0; ib < 2; ib++) {
#pragma unroll
            for (int i = 0; i < 4; i++) {
                const int m = m0 + ib * 64 + ty * 4 + i;
                float4 v;
                v.x = acc[ib * 4 + i][jb * 4 + 0] + bv4.x;
                v.y = acc[ib * 4 + i][jb * 4 + 1] + bv4.y;
                v.z = acc[ib * 4 + i][jb * 4 + 2] + bv4.z;
                v.w = acc[ib * 4 + i][jb * 4 + 3] + bv4.w;
                *(float4*)(out + (size_t)m * D_MODEL + n0 + jb * 64 + tx * 4) = v;
            }
        }
    }
}

// ---------------------------------------------------------------------------
// kernel_launch — graph-capturable, allocation-free.
// Inputs: hidden_state, Wq, Wk, Wv, bq, bk, bv, Wo, bo
// ---------------------------------------------------------------------------
extern "C" void kernel_launch(void* const* d_in, const int* in_sizes, int n_in,
                              void* d_out, int out_size)
{
    const float* X  = (const float*)d_in[0];
    const float* Wq = (const float*)d_in[1];
    const float* Wk = (const float*)d_in[2];
    const float* Wv = (const float*)d_in[3];
    const float* bq = (const float*)d_in[4];
    const float* bk = (const float*)d_in[5];
    const float* bv = (const float*)d_in[6];
    const float* Wo = (const float*)d_in[7];
    const float* bo = (const float*)d_in[8];
    float* out = (float*)d_out;

    cudaFuncSetAttribute(attn_kernel,
                         cudaFuncAttributeMaxDynamicSharedMemorySize,
                         ATT_SMEM_BYTES);

    // 1) QKV projections (128x128 tiles, head pair per block)
    {
        dim3 grid(MROWS / 128, 24);
        qkv_kernel<<<grid, 256>>>(X, Wq, Wk, Wv, bq, bk, bv);
    }
    // 2) causal flash attention
    {
        dim3 grid(SEQ / 128, BATCH * N_HEADS);
        attn_kernel<<<grid, 256, ATT_SMEM_BYTES>>>();
    }
    // 3) output projection (128x128 tiles)
    {
        dim3 grid(MROWS / 128, D_MODEL / 128);
        oproj_kernel<<<grid, 256>>>(Wo, bo, out);
    }
}